// round 8
// baseline (speedup 1.0000x reference)
#include <cuda_runtime.h>
#include <math.h>

#define NG    64
#define ATOMS 32
#define NN    2048
#define HID   128
#define FEAT  64

// ---------------- scratch (device globals; no allocations allowed) ----------------
__device__ float d_isl[NG];
__device__ float d_x[NN * HID];
__device__ float d_q[NN * HID];
__device__ float d_k[NN * HID];
__device__ float d_v[NN * HID];
__device__ float d_vals[NN * HID];
// packed weights (k-major, zero-padded, values stored as tf32 bit patterns)
__device__ float d_Wq[128 * 384];
__device__ float d_Wp0[128 * 128];   // [k][o], o>=106 zero
__device__ float d_Wp1[128 * 128];   // [k][o], k>=106 or o>=85 zero
__device__ float d_Wp2[128 * 64];    // [k][o], k>=85 zero
__device__ float d_Bp0[128];
__device__ float d_Bp1[128];

__device__ __forceinline__ unsigned f2tf32(float f) {
    unsigned u;
    asm("cvt.rna.tf32.f32 %0, %1;" : "=r"(u) : "f"(f));
    return u;
}

__device__ __forceinline__ void mma_tf32(float c[4], const unsigned a[4],
                                         unsigned b0, unsigned b1) {
    asm volatile(
        "mma.sync.aligned.m16n8k8.row.col.f32.tf32.tf32.f32 "
        "{%0,%1,%2,%3}, {%4,%5,%6,%7}, {%8,%9}, {%0,%1,%2,%3};"
        : "+f"(c[0]), "+f"(c[1]), "+f"(c[2]), "+f"(c[3])
        : "r"(a[0]), "r"(a[1]), "r"(a[2]), "r"(a[3]), "r"(b0), "r"(b1));
}

// ---------------- K0: setup = prep (blocks 0..63) + repack->tf32 (rest) --------
__global__ void k_setup(const float* __restrict__ h,
                        const float* __restrict__ next_type,
                        const float* __restrict__ W_emb,
                        const int* __restrict__ batch,
                        const float* __restrict__ Wqkv,
                        const float* __restrict__ Wd0, const float* __restrict__ bd0,
                        const float* __restrict__ Wd1, const float* __restrict__ bd1,
                        const float* __restrict__ Wd2) {
    int b = blockIdx.x, t = threadIdx.x;
    if (b < NG) {
        __shared__ float nt[FEAT];
        __shared__ float emb[HID];
        __shared__ int sc[256];
        int g = b;
        int base = g * ATOMS;
        if (t < FEAT) nt[t] = next_type[g * FEAT + t];
        __syncthreads();
        if (t < HID) {
            const float* w = W_emb + t * FEAT;
            float acc = 0.f;
#pragma unroll
            for (int f = 0; f < FEAT; f++) acc += nt[f] * w[f];
            emb[t] = acc;
        }
        int cnt = 0;
#pragma unroll
        for (int i = t; i < NN; i += 256) cnt += (batch[i] == g) ? 1 : 0;
        sc[t] = cnt;
        __syncthreads();
        for (int s = 128; s > 0; s >>= 1) {
            if (t < s) sc[t] += sc[t + s];
            __syncthreads();
        }
        if (t == 0) d_isl[g] = rsqrtf((float)sc[0]);
#pragma unroll
        for (int v = 0; v < 4; v++) {
            int lin = t + v * 256;
            int r = lin >> 5, kv = lin & 31;
            float4 hv = *(const float4*)&h[(base + r) * HID + kv * 4];
            float4 ev = *(const float4*)&emb[kv * 4];
            float4 o;
            o.x = hv.x * ev.x; o.y = hv.y * ev.y; o.z = hv.z * ev.z; o.w = hv.w * ev.w;
            *(float4*)&d_x[(base + r) * HID + kv * 4] = o;
        }
    } else {
        int idx = (b - NG) * 256 + t;
        if (idx < 49152) {
            int k = idx / 384, o = idx - k * 384;
            d_Wq[idx] = __uint_as_float(f2tf32(Wqkv[o * 128 + k]));
        } else if (idx < 65536) {
            int e = idx - 49152;
            int k = e >> 7, o = e & 127;
            d_Wp0[e] = (o < 106) ? __uint_as_float(f2tf32(Wd0[o * 128 + k])) : 0.f;
        } else if (idx < 81920) {
            int e = idx - 65536;
            int k = e >> 7, o = e & 127;
            d_Wp1[e] = (o < 85 && k < 106) ? __uint_as_float(f2tf32(Wd1[o * 106 + k])) : 0.f;
        } else if (idx < 90112) {
            int e = idx - 81920;
            int k = e >> 6, o = e & 63;
            d_Wp2[e] = (k < 85) ? __uint_as_float(f2tf32(Wd2[o * 85 + k])) : 0.f;
        } else if (idx < 90240) {
            int e = idx - 90112;
            d_Bp0[e] = (e < 106) ? bd0[e] : 0.f;
        } else if (idx < 90368) {
            int e = idx - 90240;
            d_Bp1[e] = (e < 85) ? bd1[e] : 0.f;
        }
    }
}

// ---------------- K1: qkv via tf32 MMA: 16 rows x 64 cols, 128 threads ---------
// dyn smem floats: Ws[128][72] + As[16][132]
__global__ void __launch_bounds__(128)
k_qkv(const float* __restrict__ Bp) {
    extern __shared__ float sm[];
    float* Ws = sm;                // [128][72]
    float* As = sm + 128 * 72;     // [16][132]
    int tid = threadIdx.x;
    int rb = blockIdx.y * 16;
    int cb = blockIdx.x * 64;

#pragma unroll
    for (int lin = tid; lin < 128 * 16; lin += 128) {
        int k = lin >> 4, cq = lin & 15;
        *(float4*)&Ws[k * 72 + cq * 4] = *(const float4*)&d_Wq[k * 384 + cb + cq * 4];
    }
#pragma unroll
    for (int lin = tid; lin < 16 * 32; lin += 128) {
        int r = lin >> 5, q = lin & 31;
        float4 av = *(const float4*)&d_x[(rb + r) * 128 + q * 4];
        uint4 tv;
        tv.x = f2tf32(av.x); tv.y = f2tf32(av.y);
        tv.z = f2tf32(av.z); tv.w = f2tf32(av.w);
        *(uint4*)&As[r * 132 + q * 4] = tv;
    }
    __syncthreads();

    int warp = tid >> 5, lane = tid & 31;
    int gid = lane >> 2, tig = lane & 3;

    const unsigned* Asu = (const unsigned*)As;
    const unsigned* Wsu = (const unsigned*)Ws;
    int nb = warp * 16 + gid;
    float c[2][4] = {};
#pragma unroll
    for (int s = 0; s < 16; s++) {
        int kk = s * 8 + tig;
        unsigned a[4];
        a[0] = Asu[gid * 132 + kk];
        a[1] = Asu[(gid + 8) * 132 + kk];
        a[2] = Asu[gid * 132 + kk + 4];
        a[3] = Asu[(gid + 8) * 132 + kk + 4];
        unsigned b00 = Wsu[kk * 72 + nb];
        unsigned b01 = Wsu[(kk + 4) * 72 + nb];
        unsigned b10 = Wsu[kk * 72 + nb + 8];
        unsigned b11 = Wsu[(kk + 4) * 72 + nb + 8];
        mma_tf32(c[0], a, b00, b01);
        mma_tf32(c[1], a, b10, b11);
    }

    int row0 = rb + gid, row1 = rb + gid + 8;
#pragma unroll
    for (int nt = 0; nt < 2; nt++) {
        int cg = cb + warp * 16 + nt * 8 + tig * 2;
        int which = cg >> 7;
        int lc = cg & 127;
        float* outb = (which == 0) ? d_q : ((which == 1) ? d_k : d_v);
        float bq0 = Bp[cg], bq1 = Bp[cg + 1];
        float2 o0, o1;
        o0.x = c[nt][0] + bq0; o0.y = c[nt][1] + bq1;
        o1.x = c[nt][2] + bq0; o1.y = c[nt][3] + bq1;
        *(float2*)&outb[row0 * 128 + lc] = o0;
        *(float2*)&outb[row1 * 128 + lc] = o1;
    }
}

// ---------------- K2: fused attention, 4 blocks per graph (8 rows each) --------
__global__ void k_attn(const float* __restrict__ pos,
                       const float* __restrict__ W_t, const float* __restrict__ b_t,
                       const float* __restrict__ W_g, const float* __restrict__ b_g) {
    extern __shared__ float sm[];
    float* sQt  = sm;             // [128][9]
    float* sKt  = sm + 1152;      // [128][32]
    float* sV   = sm + 5248;      // [32][128]
    float* sL   = sm + 9344;      // [8][32]
    float* sWg  = sm + 9600;      // 128
    float* sPos = sm + 9728;      // 96
    float* sGate= sm + 9824;      // 8
    float* sWt  = sm + 9832;      // 32

    int bid = blockIdx.x, tid = threadIdx.x;
    int g = bid >> 2, quarter = bid & 3;
    int base = g * ATOMS;
    int rbase = quarter * 8;

    {
        int kq = tid >> 3, r = tid & 7;
        float4 qa = *(const float4*)&d_q[(base + rbase + r) * HID + kq * 4];
        sQt[(kq * 4 + 0) * 9 + r] = qa.x;
        sQt[(kq * 4 + 1) * 9 + r] = qa.y;
        sQt[(kq * 4 + 2) * 9 + r] = qa.z;
        sQt[(kq * 4 + 3) * 9 + r] = qa.w;
    }
#pragma unroll
    for (int v = 0; v < 4; v++) {
        int lin = tid + v * 256;
        int r = lin & 31, kq = lin >> 5;
        float4 ka = *(const float4*)&d_k[(base + r) * HID + kq * 4];
        sKt[(kq * 4 + 0) * 32 + r] = ka.x;
        sKt[(kq * 4 + 1) * 32 + r] = ka.y;
        sKt[(kq * 4 + 2) * 32 + r] = ka.z;
        sKt[(kq * 4 + 3) * 32 + r] = ka.w;
    }
#pragma unroll
    for (int v = 0; v < 4; v++) {
        int lin = tid + v * 256;
        int r = lin >> 5, kv = lin & 31;
        *(float4*)&sV[r * 128 + kv * 4] = *(const float4*)&d_v[(base + r) * HID + kv * 4];
    }
    if (tid < 128) sWg[tid] = W_g[tid];
    if (tid < 96) sPos[tid] = pos[base * 3 + tid];
    if (tid < 32) sWt[tid] = W_t[tid];
    __syncthreads();

    int w = tid >> 5, lane = tid & 31;
    float invs = d_isl[g];
    float bgv = b_g[0];

    {
        const float* xr = d_x + (base + rbase + w) * HID;
        float p = 0.f;
#pragma unroll
        for (int k = lane; k < HID; k += 32) p += xr[k] * sWg[k];
#pragma unroll
        for (int o = 16; o; o >>= 1) p += __shfl_xor_sync(~0u, p, o);
        if (lane == 0) sGate[w] = 1.f / (1.f + __expf(-(p + bgv)));
    }

    int i = tid >> 5;
    int j = lane;
    float qk_e = 0.f, qk_o = 0.f;
#pragma unroll 8
    for (int k = 0; k < HID; k += 2) {
        qk_e += sQt[k * 9 + i] * sKt[k * 32 + j];
        qk_o += sQt[(k + 1) * 9 + i] * sKt[(k + 1) * 32 + j];
    }
    float qk = qk_e + qk_o;
    float btv = b_t[0];
    int gi = rbase + i;
    float dx = sPos[gi * 3 + 0] - sPos[j * 3 + 0];
    float dy = sPos[gi * 3 + 1] - sPos[j * 3 + 1];
    float dz = sPos[gi * 3 + 2] - sPos[j * 3 + 2];
    float d = sqrtf(fmaxf(dx * dx + dy * dy + dz * dz, 1e-12f));
    const float step = 10.f / 31.f;
    int b0 = __float2int_rn(d * (31.f / 10.f));
    int bs = min(max(b0 - 4, 0), 24);
    float t = btv;
#pragma unroll
    for (int bb = 0; bb < 8; bb++) {
        int b = bs + bb;
        float diff = d - (float)b * step;
        t += __expf(-10.f * diff * diff) * sWt[b];
    }
    sL[i * 32 + j] = qk * invs + t;
    __syncthreads();

    {
        float vv = sL[w * 32 + lane];
        float m = vv;
#pragma unroll
        for (int o = 16; o; o >>= 1) m = fmaxf(m, __shfl_xor_sync(~0u, m, o));
        float e = __expf(vv - m);
        float s = e;
#pragma unroll
        for (int o = 16; o; o >>= 1) s += __shfl_xor_sync(~0u, s, o);
        sL[w * 32 + lane] = e / s;
    }
    __syncthreads();

    {
        int rg = tid >> 5, cg = tid & 31;
        int c0 = cg * 4;
        float a0 = 0.f, a1 = 0.f, a2 = 0.f, a3 = 0.f;
#pragma unroll 8
        for (int jj = 0; jj < 32; jj++) {
            float p = sL[rg * 32 + jj];
            float4 vv = *(const float4*)&sV[jj * 128 + c0];
            a0 += p * vv.x; a1 += p * vv.y; a2 += p * vv.z; a3 += p * vv.w;
        }
        int grow = base + rbase + rg;
        float gg = sGate[rg];
        float4 xr = *(const float4*)&d_x[grow * HID + c0];
        float4 o;
        o.x = a0 * gg + xr.x; o.y = a1 * gg + xr.y;
        o.z = a2 * gg + xr.z; o.w = a3 * gg + xr.w;
        *(float4*)&d_vals[grow * HID + c0] = o;
    }
}

// ---------------- K3: fused 3-layer dense head + log_softmax (tf32 MMA) --------
// 16 rows/block, grid 128, 128 threads. All weights in smem.
// smem floats: W0[128][136]=17408 @0, W1[112][136]=15232 @17408,
//   W2[88][72]=6336 @32640, A[16][132]=2112 @38976, Y0[16][132]=2112 @41088,
//   Y1[16][132]=2112 @43200, B0 @45312, B1 @45440, B2 @45568 -> 45632 (182528 B)
__global__ void __launch_bounds__(128)
k_mlp3(const float* __restrict__ bd2, float* __restrict__ out) {
    extern __shared__ float sm[];
    float* W0 = sm;
    float* W1 = sm + 17408;
    float* W2 = sm + 32640;
    float* A  = sm + 38976;
    float* Y0 = sm + 41088;
    float* Y1 = sm + 43200;
    float* B0 = sm + 45312;
    float* B1 = sm + 45440;
    float* B2 = sm + 45568;

    int tid = threadIdx.x;
    int rb = blockIdx.x * 16;

    // stage W0: 128 rows x 128 cols -> stride 136
#pragma unroll 8
    for (int lin = tid; lin < 4096; lin += 128) {
        int k = lin >> 5, cq = lin & 31;
        *(float4*)&W0[k * 136 + cq * 4] = *(const float4*)&d_Wp0[k * 128 + cq * 4];
    }
    // stage W1: 112 rows x 128 cols -> stride 136
#pragma unroll 7
    for (int lin = tid; lin < 3584; lin += 128) {
        int k = lin >> 5, cq = lin & 31;
        *(float4*)&W1[k * 136 + cq * 4] = *(const float4*)&d_Wp1[k * 128 + cq * 4];
    }
    // stage W2: 88 rows x 64 cols -> stride 72
#pragma unroll 4
    for (int lin = tid; lin < 1408; lin += 128) {
        int k = lin >> 4, cq = lin & 15;
        *(float4*)&W2[k * 72 + cq * 4] = *(const float4*)&d_Wp2[k * 64 + cq * 4];
    }
    // stage A: 16 rows x 128, tf32 convert, stride 132
#pragma unroll 4
    for (int lin = tid; lin < 512; lin += 128) {
        int r = lin >> 5, q = lin & 31;
        float4 av = *(const float4*)&d_vals[(rb + r) * 128 + q * 4];
        uint4 tv;
        tv.x = f2tf32(av.x); tv.y = f2tf32(av.y);
        tv.z = f2tf32(av.z); tv.w = f2tf32(av.w);
        *(uint4*)&A[r * 132 + q * 4] = tv;
    }
    if (tid < 128) B0[tid] = d_Bp0[tid];
    if (tid < 128) B1[tid] = d_Bp1[tid];
    if (tid < 64) B2[tid] = bd2[tid];
    __syncthreads();

    int warp = tid >> 5, lane = tid & 31;
    int gid = lane >> 2, tig = lane & 3;

    // ---- layer 0: A[16x128] @ W0 -> SiLU -> Y0 (tf32) ; warp covers 32 cols ----
    {
        const unsigned* Au = (const unsigned*)A;
        const unsigned* Wu = (const unsigned*)W0;
        float c[4][4] = {};
#pragma unroll
        for (int s = 0; s < 16; s++) {
            int kk = s * 8 + tig;
            unsigned a[4];
            a[0] = Au[gid * 132 + kk];
            a[1] = Au[(gid + 8) * 132 + kk];
            a[2] = Au[gid * 132 + kk + 4];
            a[3] = Au[(gid + 8) * 132 + kk + 4];
#pragma unroll
            for (int nt = 0; nt < 4; nt++) {
                int nb = warp * 32 + nt * 8 + gid;
                mma_tf32(c[nt], a, Wu[kk * 136 + nb], Wu[(kk + 4) * 136 + nb]);
            }
        }
        unsigned* Yu = (unsigned*)Y0;
#pragma unroll
        for (int nt = 0; nt < 4; nt++) {
            int col = warp * 32 + nt * 8 + tig * 2;
            float z0 = c[nt][0] + B0[col], z1 = c[nt][1] + B0[col + 1];
            float z2 = c[nt][2] + B0[col], z3 = c[nt][3] + B0[col + 1];
            Yu[gid * 132 + col]           = f2tf32(z0 / (1.f + __expf(-z0)));
            Yu[gid * 132 + col + 1]       = f2tf32(z1 / (1.f + __expf(-z1)));
            Yu[(gid + 8) * 132 + col]     = f2tf32(z2 / (1.f + __expf(-z2)));
            Yu[(gid + 8) * 132 + col + 1] = f2tf32(z3 / (1.f + __expf(-z3)));
        }
    }
    __syncthreads();

    // ---- layer 1: Y0[16x112] @ W1 -> SiLU -> Y1 (tf32) ----
    {
        const unsigned* Au = (const unsigned*)Y0;
        const unsigned* Wu = (const unsigned*)W1;
        float c[4][4] = {};
#pragma unroll
        for (int s = 0; s < 14; s++) {
            int kk = s * 8 + tig;
            unsigned a[4];
            a[0] = Au[gid * 132 + kk];
            a[1] = Au[(gid + 8) * 132 + kk];
            a[2] = Au[gid * 132 + kk + 4];
            a[3] = Au[(gid + 8) * 132 + kk + 4];
#pragma unroll
            for (int nt = 0; nt < 4; nt++) {
                int nb = warp * 32 + nt * 8 + gid;
                mma_tf32(c[nt], a, Wu[kk * 136 + nb], Wu[(kk + 4) * 136 + nb]);
            }
        }
        unsigned* Yu = (unsigned*)Y1;
#pragma unroll
        for (int nt = 0; nt < 4; nt++) {
            int col = warp * 32 + nt * 8 + tig * 2;
            float z0 = c[nt][0] + B1[col], z1 = c[nt][1] + B1[col + 1];
            float z2 = c[nt][2] + B1[col], z3 = c[nt][3] + B1[col + 1];
            Yu[gid * 132 + col]           = f2tf32(z0 / (1.f + __expf(-z0)));
            Yu[gid * 132 + col + 1]       = f2tf32(z1 / (1.f + __expf(-z1)));
            Yu[(gid + 8) * 132 + col]     = f2tf32(z2 / (1.f + __expf(-z2)));
            Yu[(gid + 8) * 132 + col + 1] = f2tf32(z3 / (1.f + __expf(-z3)));
        }
    }
    __syncthreads();

    // ---- layer 2: Y1[16x88] @ W2 -> logits[16][64] -> log_softmax -> out ----
    {
        const unsigned* Au = (const unsigned*)Y1;
        const unsigned* Wu = (const unsigned*)W2;
        float c[2][4] = {};
#pragma unroll
        for (int s = 0; s < 11; s++) {
            int kk = s * 8 + tig;
            unsigned a[4];
            a[0] = Au[gid * 132 + kk];
            a[1] = Au[(gid + 8) * 132 + kk];
            a[2] = Au[gid * 132 + kk + 4];
            a[3] = Au[(gid + 8) * 132 + kk + 4];
#pragma unroll
            for (int nt = 0; nt < 2; nt++) {
                int nb = warp * 16 + nt * 8 + gid;
                mma_tf32(c[nt], a, Wu[kk * 72 + nb], Wu[(kk + 4) * 72 + nb]);
            }
        }
        float* sY = Y0;   // reuse, stride 66
#pragma unroll
        for (int nt = 0; nt < 2; nt++) {
            int lc = warp * 16 + nt * 8 + tig * 2;
            float bq0 = B2[lc], bq1 = B2[lc + 1];
            float2 o;
            o.x = c[nt][0] + bq0; o.y = c[nt][1] + bq1;
            *(float2*)&sY[gid * 66 + lc] = o;
            o.x = c[nt][2] + bq0; o.y = c[nt][3] + bq1;
            *(float2*)&sY[(gid + 8) * 66 + lc] = o;
        }
        __syncthreads();
#pragma unroll
        for (int rr = 0; rr < 4; rr++) {
            int r = warp * 4 + rr;
            float v0 = sY[r * 66 + lane];
            float v1 = sY[r * 66 + 32 + lane];
            float m = fmaxf(v0, v1);
#pragma unroll
            for (int o = 16; o; o >>= 1) m = fmaxf(m, __shfl_xor_sync(~0u, m, o));
            float s = __expf(v0 - m) + __expf(v1 - m);
#pragma unroll
            for (int o = 16; o; o >>= 1) s += __shfl_xor_sync(~0u, s, o);
            float ls = logf(s) + m;
            out[(rb + r) * 64 + lane] = v0 - ls;
            out[(rb + r) * 64 + 32 + lane] = v1 - ls;
        }
    }
}

// ---------------- launch ----------------
extern "C" void kernel_launch(void* const* d_in, const int* in_sizes, int n_in,
                              void* d_out, int out_size) {
    const float* h     = (const float*)d_in[0];
    const float* pos   = (const float*)d_in[1];
    const float* nt    = (const float*)d_in[2];
    const int*   batch = (const int*)d_in[3];
    const float* W_emb = (const float*)d_in[4];
    const float* W_qkv = (const float*)d_in[5];
    const float* b_qkv = (const float*)d_in[6];
    // d_in[7]=W_b, d_in[8]=b_b : per-row bias, drops out of softmax
    const float* W_g   = (const float*)d_in[9];
    const float* b_g   = (const float*)d_in[10];
    const float* W_t   = (const float*)d_in[11];
    const float* b_t   = (const float*)d_in[12];
    const float* W_d0  = (const float*)d_in[13];
    const float* b_d0  = (const float*)d_in[14];
    const float* W_d1  = (const float*)d_in[15];
    const float* b_d1  = (const float*)d_in[16];
    const float* W_d2  = (const float*)d_in[17];
    const float* b_d2  = (const float*)d_in[18];
    float* out = (float*)d_out;

    cudaFuncSetAttribute(k_attn, cudaFuncAttributeMaxDynamicSharedMemorySize, 48 * 1024);
    cudaFuncSetAttribute(k_mlp3, cudaFuncAttributeMaxDynamicSharedMemorySize, 182528);

    const int smem_qkv = (128 * 72 + 16 * 132) * 4;   // 45312

    k_setup<<<NG + 354, 256>>>(h, nt, W_emb, batch, W_qkv, W_d0, b_d0, W_d1, b_d1, W_d2);
    k_qkv<<<dim3(6, 128), 128, smem_qkv>>>(b_qkv);
    k_attn<<<NG * 4, 256, 9864 * 4>>>(pos, W_t, b_t, W_g, b_g);
    k_mlp3<<<NN / 16, 128, 182528>>>(b_d2, out);
}

// round 14
// speedup vs baseline: 1.4857x; 1.4857x over previous
#include <cuda_runtime.h>
#include <math.h>

#define NG    64
#define ATOMS 32
#define NN    2048
#define HID   128
#define FEAT  64

// ---------------- scratch (device globals; no allocations allowed) ----------------
__device__ float d_isl[NG];
__device__ float d_x[NN * HID];
__device__ float d_q[NN * HID];
__device__ float d_k[NN * HID];
__device__ float d_v[NN * HID];
__device__ float d_vals[NN * HID];
__device__ float d_y0[NN * 128];
__device__ float d_y1[NN * 128];
// packed weights (k-major, zero-padded, values stored as tf32 bit patterns)
__device__ float d_Wq[128 * 384];
__device__ float d_Wp0[128 * 128];   // [k][o], o>=106 zero
__device__ float d_Wp1[128 * 128];   // [k][o], k>=106 or o>=85 zero
__device__ float d_Wp2[128 * 64];    // [k][o], k>=85 zero
__device__ float d_Bp0[128];
__device__ float d_Bp1[128];

__device__ __forceinline__ unsigned f2tf32(float f) {
    unsigned u;
    asm("cvt.rna.tf32.f32 %0, %1;" : "=r"(u) : "f"(f));
    return u;
}

__device__ __forceinline__ void mma_tf32(float c[4], const unsigned a[4],
                                         unsigned b0, unsigned b1) {
    asm volatile(
        "mma.sync.aligned.m16n8k8.row.col.f32.tf32.tf32.f32 "
        "{%0,%1,%2,%3}, {%4,%5,%6,%7}, {%8,%9}, {%0,%1,%2,%3};"
        : "+f"(c[0]), "+f"(c[1]), "+f"(c[2]), "+f"(c[3])
        : "r"(a[0]), "r"(a[1]), "r"(a[2]), "r"(a[3]), "r"(b0), "r"(b1));
}

// ---------------- K0: setup = prep (blocks 0..63) + repack->tf32 (rest) --------
__global__ void k_setup(const float* __restrict__ h,
                        const float* __restrict__ next_type,
                        const float* __restrict__ W_emb,
                        const int* __restrict__ batch,
                        const float* __restrict__ Wqkv,
                        const float* __restrict__ Wd0, const float* __restrict__ bd0,
                        const float* __restrict__ Wd1, const float* __restrict__ bd1,
                        const float* __restrict__ Wd2) {
    int b = blockIdx.x, t = threadIdx.x;
    if (b < NG) {
        __shared__ float nt[FEAT];
        __shared__ float emb[HID];
        __shared__ int sc[256];
        int g = b;
        int base = g * ATOMS;
        if (t < FEAT) nt[t] = next_type[g * FEAT + t];
        __syncthreads();
        if (t < HID) {
            const float* w = W_emb + t * FEAT;
            float acc = 0.f;
#pragma unroll
            for (int f = 0; f < FEAT; f++) acc += nt[f] * w[f];
            emb[t] = acc;
        }
        int cnt = 0;
#pragma unroll
        for (int i = t; i < NN; i += 256) cnt += (batch[i] == g) ? 1 : 0;
        sc[t] = cnt;
        __syncthreads();
        for (int s = 128; s > 0; s >>= 1) {
            if (t < s) sc[t] += sc[t + s];
            __syncthreads();
        }
        if (t == 0) d_isl[g] = rsqrtf((float)sc[0]);
#pragma unroll
        for (int v = 0; v < 4; v++) {
            int lin = t + v * 256;
            int r = lin >> 5, kv = lin & 31;
            float4 hv = *(const float4*)&h[(base + r) * HID + kv * 4];
            float4 ev = *(const float4*)&emb[kv * 4];
            float4 o;
            o.x = hv.x * ev.x; o.y = hv.y * ev.y; o.z = hv.z * ev.z; o.w = hv.w * ev.w;
            *(float4*)&d_x[(base + r) * HID + kv * 4] = o;
        }
    } else {
        int idx = (b - NG) * 256 + t;
        if (idx < 49152) {
            int k = idx / 384, o = idx - k * 384;
            d_Wq[idx] = __uint_as_float(f2tf32(Wqkv[o * 128 + k]));
        } else if (idx < 65536) {
            int e = idx - 49152;
            int k = e >> 7, o = e & 127;
            d_Wp0[e] = (o < 106) ? __uint_as_float(f2tf32(Wd0[o * 128 + k])) : 0.f;
        } else if (idx < 81920) {
            int e = idx - 65536;
            int k = e >> 7, o = e & 127;
            d_Wp1[e] = (o < 85 && k < 106) ? __uint_as_float(f2tf32(Wd1[o * 106 + k])) : 0.f;
        } else if (idx < 90112) {
            int e = idx - 81920;
            int k = e >> 6, o = e & 63;
            d_Wp2[e] = (k < 85) ? __uint_as_float(f2tf32(Wd2[o * 85 + k])) : 0.f;
        } else if (idx < 90240) {
            int e = idx - 90112;
            d_Bp0[e] = (e < 106) ? bd0[e] : 0.f;
        } else if (idx < 90368) {
            int e = idx - 90240;
            d_Bp1[e] = (e < 85) ? bd1[e] : 0.f;
        }
    }
}

// ---------------- tf32 MMA GEMM: 16 rows x 64 cols per block, 128 threads ------
// KSTEPS: k-depth/8.  WGS: global W row stride.  CS: C row stride.
// ACT: 0 = SiLU store, 1 = log_softmax (CS==64, gridDim.x==1), 2 = qkv routing
// dyn smem floats: Ws[KSTEPS*8][72] + As[16][132]
template<int KSTEPS, int WGS, int CS, int ACT>
__global__ void __launch_bounds__(128)
k_gmma(const float* __restrict__ A, const float* __restrict__ Wp,
       const float* __restrict__ Bp, float* __restrict__ C) {
    extern __shared__ float sm[];
    float* Ws = sm;                      // [KSTEPS*8][72] tf32 bits
    float* As = sm + KSTEPS * 8 * 72;    // [16][132] tf32 bits
    int tid = threadIdx.x;
    int rb = blockIdx.y * 16;
    int cb = blockIdx.x * 64;

    // stage W (already tf32-packed): KSTEPS*8 rows x 64 cols
#pragma unroll
    for (int lin = tid; lin < KSTEPS * 8 * 16; lin += 128) {
        int k = lin >> 4, cq = lin & 15;
        float4 wv = *(const float4*)&Wp[k * WGS + cb + cq * 4];
        *(float4*)&Ws[k * 72 + cq * 4] = wv;
    }
    // stage A with fp32->tf32 convert: 16 rows x KSTEPS*8 cols
#pragma unroll
    for (int lin = tid; lin < 16 * KSTEPS * 2; lin += 128) {
        int r = lin / (KSTEPS * 2), q = lin - r * (KSTEPS * 2);
        float4 av = *(const float4*)&A[(rb + r) * 128 + q * 4];
        uint4 tv;
        tv.x = f2tf32(av.x); tv.y = f2tf32(av.y);
        tv.z = f2tf32(av.z); tv.w = f2tf32(av.w);
        *(uint4*)&As[r * 132 + q * 4] = tv;
    }
    __syncthreads();

    int warp = tid >> 5, lane = tid & 31;
    int gid = lane >> 2, tig = lane & 3;

    const unsigned* Asu = (const unsigned*)As;
    const unsigned* Wsu = (const unsigned*)Ws;
    int nb = warp * 16 + gid;            // base B column for this thread
    float c[2][4] = {};
#pragma unroll
    for (int s = 0; s < KSTEPS; s++) {
        int kk = s * 8 + tig;
        unsigned a[4];
        a[0] = Asu[gid * 132 + kk];
        a[1] = Asu[(gid + 8) * 132 + kk];
        a[2] = Asu[gid * 132 + kk + 4];
        a[3] = Asu[(gid + 8) * 132 + kk + 4];
        unsigned b00 = Wsu[kk * 72 + nb];
        unsigned b01 = Wsu[(kk + 4) * 72 + nb];
        unsigned b10 = Wsu[kk * 72 + nb + 8];
        unsigned b11 = Wsu[(kk + 4) * 72 + nb + 8];
        mma_tf32(c[0], a, b00, b01);
        mma_tf32(c[1], a, b10, b11);
    }

    int row0 = rb + gid, row1 = rb + gid + 8;

    if (ACT == 2) {
        // qkv: route whole 64-col block to q/k/v
#pragma unroll
        for (int nt = 0; nt < 2; nt++) {
            int cg = cb + warp * 16 + nt * 8 + tig * 2;
            int which = cg >> 7;
            int lc = cg & 127;
            float* outb = (which == 0) ? d_q : ((which == 1) ? d_k : d_v);
            float bq0 = Bp[cg], bq1 = Bp[cg + 1];
            float2 o0, o1;
            o0.x = c[nt][0] + bq0; o0.y = c[nt][1] + bq1;
            o1.x = c[nt][2] + bq0; o1.y = c[nt][3] + bq1;
            *(float2*)&outb[row0 * 128 + lc] = o0;
            *(float2*)&outb[row1 * 128 + lc] = o1;
        }
    } else if (ACT == 0) {
#pragma unroll
        for (int nt = 0; nt < 2; nt++) {
            int cg = cb + warp * 16 + nt * 8 + tig * 2;
            float bq0 = Bp[cg], bq1 = Bp[cg + 1];
            float z, o0x, o0y, o1x, o1y;
            z = c[nt][0] + bq0; o0x = z / (1.f + __expf(-z));
            z = c[nt][1] + bq1; o0y = z / (1.f + __expf(-z));
            z = c[nt][2] + bq0; o1x = z / (1.f + __expf(-z));
            z = c[nt][3] + bq1; o1y = z / (1.f + __expf(-z));
            float2 a2;
            a2.x = o0x; a2.y = o0y;
            *(float2*)&C[row0 * CS + cg] = a2;
            a2.x = o1x; a2.y = o1y;
            *(float2*)&C[row1 * CS + cg] = a2;
        }
    } else {
        // ACT == 1: bias, stage to smem, block log_softmax over 64 cols
        __syncthreads();             // done reading Ws; reuse as Y[16][66]
        float* sY = Ws;
#pragma unroll
        for (int nt = 0; nt < 2; nt++) {
            int lc = warp * 16 + nt * 8 + tig * 2;
            float bq0 = Bp[lc], bq1 = Bp[lc + 1];
            float2 o;
            o.x = c[nt][0] + bq0; o.y = c[nt][1] + bq1;
            *(float2*)&sY[gid * 66 + lc] = o;
            o.x = c[nt][2] + bq0; o.y = c[nt][3] + bq1;
            *(float2*)&sY[(gid + 8) * 66 + lc] = o;
        }
        __syncthreads();
#pragma unroll
        for (int rr = 0; rr < 4; rr++) {
            int r = warp * 4 + rr;
            float v0 = sY[r * 66 + lane];
            float v1 = sY[r * 66 + 32 + lane];
            float m = fmaxf(v0, v1);
#pragma unroll
            for (int o = 16; o; o >>= 1) m = fmaxf(m, __shfl_xor_sync(~0u, m, o));
            float s = __expf(v0 - m) + __expf(v1 - m);
#pragma unroll
            for (int o = 16; o; o >>= 1) s += __shfl_xor_sync(~0u, s, o);
            float ls = logf(s) + m;
            C[(rb + r) * 64 + lane] = v0 - ls;
            C[(rb + r) * 64 + 32 + lane] = v1 - ls;
        }
    }
}

// ------- tf32 MMA GEMM, narrow tile: 16 rows x 32 cols, 64 threads (2 warps) ----
// For the SiLU mlp layers: doubles grid size for occupancy.
// dyn smem floats: Ws[KSTEPS*8][40] + As[16][132]
template<int KSTEPS, int WGS, int CS>
__global__ void __launch_bounds__(64)
k_gmma32(const float* __restrict__ A, const float* __restrict__ Wp,
         const float* __restrict__ Bp, float* __restrict__ C) {
    extern __shared__ float sm[];
    float* Ws = sm;                      // [KSTEPS*8][40] tf32 bits
    float* As = sm + KSTEPS * 8 * 40;    // [16][132] tf32 bits
    int tid = threadIdx.x;
    int rb = blockIdx.y * 16;
    int cb = blockIdx.x * 32;

    // stage W: KSTEPS*8 rows x 32 cols (8 float4/row)
#pragma unroll
    for (int lin = tid; lin < KSTEPS * 8 * 8; lin += 64) {
        int k = lin >> 3, cq = lin & 7;
        float4 wv = *(const float4*)&Wp[k * WGS + cb + cq * 4];
        *(float4*)&Ws[k * 40 + cq * 4] = wv;
    }
    // stage A with fp32->tf32 convert: 16 rows x KSTEPS*8 cols
#pragma unroll
    for (int lin = tid; lin < 16 * KSTEPS * 2; lin += 64) {
        int r = lin / (KSTEPS * 2), q = lin - r * (KSTEPS * 2);
        float4 av = *(const float4*)&A[(rb + r) * 128 + q * 4];
        uint4 tv;
        tv.x = f2tf32(av.x); tv.y = f2tf32(av.y);
        tv.z = f2tf32(av.z); tv.w = f2tf32(av.w);
        *(uint4*)&As[r * 132 + q * 4] = tv;
    }
    __syncthreads();

    int warp = tid >> 5, lane = tid & 31;
    int gid = lane >> 2, tig = lane & 3;

    const unsigned* Asu = (const unsigned*)As;
    const unsigned* Wsu = (const unsigned*)Ws;
    int nb = warp * 16 + gid;
    float c[2][4] = {};
#pragma unroll
    for (int s = 0; s < KSTEPS; s++) {
        int kk = s * 8 + tig;
        unsigned a[4];
        a[0] = Asu[gid * 132 + kk];
        a[1] = Asu[(gid + 8) * 132 + kk];
        a[2] = Asu[gid * 132 + kk + 4];
        a[3] = Asu[(gid + 8) * 132 + kk + 4];
        unsigned b00 = Wsu[kk * 40 + nb];
        unsigned b01 = Wsu[(kk + 4) * 40 + nb];
        unsigned b10 = Wsu[kk * 40 + nb + 8];
        unsigned b11 = Wsu[(kk + 4) * 40 + nb + 8];
        mma_tf32(c[0], a, b00, b01);
        mma_tf32(c[1], a, b10, b11);
    }

    int row0 = rb + gid, row1 = rb + gid + 8;
#pragma unroll
    for (int nt = 0; nt < 2; nt++) {
        int cg = cb + warp * 16 + nt * 8 + tig * 2;
        float bq0 = Bp[cg], bq1 = Bp[cg + 1];
        float z, o0x, o0y, o1x, o1y;
        z = c[nt][0] + bq0; o0x = z / (1.f + __expf(-z));
        z = c[nt][1] + bq1; o0y = z / (1.f + __expf(-z));
        z = c[nt][2] + bq0; o1x = z / (1.f + __expf(-z));
        z = c[nt][3] + bq1; o1y = z / (1.f + __expf(-z));
        float2 a2;
        a2.x = o0x; a2.y = o0y;
        *(float2*)&C[row0 * CS + cg] = a2;
        a2.x = o1x; a2.y = o1y;
        *(float2*)&C[row1 * CS + cg] = a2;
    }
}

// ---------------- K2: fused attention, 4 blocks per graph (8 rows each) --------
__global__ void k_attn(const float* __restrict__ pos,
                       const float* __restrict__ W_t, const float* __restrict__ b_t,
                       const float* __restrict__ W_g, const float* __restrict__ b_g) {
    extern __shared__ float sm[];
    float* sQt  = sm;             // [128][9]
    float* sKt  = sm + 1152;      // [128][32]
    float* sV   = sm + 5248;      // [32][128]
    float* sL   = sm + 9344;      // [8][32]
    float* sWg  = sm + 9600;      // 128
    float* sPos = sm + 9728;      // 96
    float* sGate= sm + 9824;      // 8
    float* sWt  = sm + 9832;      // 32

    int bid = blockIdx.x, tid = threadIdx.x;
    int g = bid >> 2, quarter = bid & 3;
    int base = g * ATOMS;
    int rbase = quarter * 8;

    {
        int kq = tid >> 3, r = tid & 7;
        float4 qa = *(const float4*)&d_q[(base + rbase + r) * HID + kq * 4];
        sQt[(kq * 4 + 0) * 9 + r] = qa.x;
        sQt[(kq * 4 + 1) * 9 + r] = qa.y;
        sQt[(kq * 4 + 2) * 9 + r] = qa.z;
        sQt[(kq * 4 + 3) * 9 + r] = qa.w;
    }
#pragma unroll
    for (int v = 0; v < 4; v++) {
        int lin = tid + v * 256;
        int r = lin & 31, kq = lin >> 5;
        float4 ka = *(const float4*)&d_k[(base + r) * HID + kq * 4];
        sKt[(kq * 4 + 0) * 32 + r] = ka.x;
        sKt[(kq * 4 + 1) * 32 + r] = ka.y;
        sKt[(kq * 4 + 2) * 32 + r] = ka.z;
        sKt[(kq * 4 + 3) * 32 + r] = ka.w;
    }
#pragma unroll
    for (int v = 0; v < 4; v++) {
        int lin = tid + v * 256;
        int r = lin >> 5, kv = lin & 31;
        *(float4*)&sV[r * 128 + kv * 4] = *(const float4*)&d_v[(base + r) * HID + kv * 4];
    }
    if (tid < 128) sWg[tid] = W_g[tid];
    if (tid < 96) sPos[tid] = pos[base * 3 + tid];
    if (tid < 32) sWt[tid] = W_t[tid];
    __syncthreads();

    int w = tid >> 5, lane = tid & 31;
    float invs = d_isl[g];
    float bgv = b_g[0];

    {
        const float* xr = d_x + (base + rbase + w) * HID;
        float p = 0.f;
#pragma unroll
        for (int k = lane; k < HID; k += 32) p += xr[k] * sWg[k];
#pragma unroll
        for (int o = 16; o; o >>= 1) p += __shfl_xor_sync(~0u, p, o);
        if (lane == 0) sGate[w] = 1.f / (1.f + __expf(-(p + bgv)));
    }

    int i = tid >> 5;
    int j = lane;
    float qk_e = 0.f, qk_o = 0.f;
#pragma unroll 8
    for (int k = 0; k < HID; k += 2) {
        qk_e += sQt[k * 9 + i] * sKt[k * 32 + j];
        qk_o += sQt[(k + 1) * 9 + i] * sKt[(k + 1) * 32 + j];
    }
    float qk = qk_e + qk_o;
    float btv = b_t[0];
    int gi = rbase + i;
    float dx = sPos[gi * 3 + 0] - sPos[j * 3 + 0];
    float dy = sPos[gi * 3 + 1] - sPos[j * 3 + 1];
    float dz = sPos[gi * 3 + 2] - sPos[j * 3 + 2];
    float d = sqrtf(fmaxf(dx * dx + dy * dy + dz * dz, 1e-12f));
    const float step = 10.f / 31.f;
    int b0 = __float2int_rn(d * (31.f / 10.f));
    int bs = min(max(b0 - 4, 0), 24);
    float t = btv;
#pragma unroll
    for (int bb = 0; bb < 8; bb++) {
        int b = bs + bb;
        float diff = d - (float)b * step;
        t += __expf(-10.f * diff * diff) * sWt[b];
    }
    sL[i * 32 + j] = qk * invs + t;
    __syncthreads();

    {
        float vv = sL[w * 32 + lane];
        float m = vv;
#pragma unroll
        for (int o = 16; o; o >>= 1) m = fmaxf(m, __shfl_xor_sync(~0u, m, o));
        float e = __expf(vv - m);
        float s = e;
#pragma unroll
        for (int o = 16; o; o >>= 1) s += __shfl_xor_sync(~0u, s, o);
        sL[w * 32 + lane] = e / s;
    }
    __syncthreads();

    {
        int rg = tid >> 5, cg = tid & 31;
        int c0 = cg * 4;
        float a0 = 0.f, a1 = 0.f, a2 = 0.f, a3 = 0.f;
#pragma unroll 8
        for (int jj = 0; jj < 32; jj++) {
            float p = sL[rg * 32 + jj];
            float4 vv = *(const float4*)&sV[jj * 128 + c0];
            a0 += p * vv.x; a1 += p * vv.y; a2 += p * vv.z; a3 += p * vv.w;
        }
        int grow = base + rbase + rg;
        float gg = sGate[rg];
        float4 xr = *(const float4*)&d_x[grow * HID + c0];
        float4 o;
        o.x = a0 * gg + xr.x; o.y = a1 * gg + xr.y;
        o.z = a2 * gg + xr.z; o.w = a3 * gg + xr.w;
        *(float4*)&d_vals[grow * HID + c0] = o;
    }
}

// ---------------- launch ----------------
extern "C" void kernel_launch(void* const* d_in, const int* in_sizes, int n_in,
                              void* d_out, int out_size) {
    const float* h     = (const float*)d_in[0];
    const float* pos   = (const float*)d_in[1];
    const float* nt    = (const float*)d_in[2];
    const int*   batch = (const int*)d_in[3];
    const float* W_emb = (const float*)d_in[4];
    const float* W_qkv = (const float*)d_in[5];
    const float* b_qkv = (const float*)d_in[6];
    // d_in[7]=W_b, d_in[8]=b_b : per-row bias, drops out of softmax
    const float* W_g   = (const float*)d_in[9];
    const float* b_g   = (const float*)d_in[10];
    const float* W_t   = (const float*)d_in[11];
    const float* b_t   = (const float*)d_in[12];
    const float* W_d0  = (const float*)d_in[13];
    const float* b_d0  = (const float*)d_in[14];
    const float* W_d1  = (const float*)d_in[15];
    const float* b_d1  = (const float*)d_in[16];
    const float* W_d2  = (const float*)d_in[17];
    const float* b_d2  = (const float*)d_in[18];
    float* out = (float*)d_out;

    float *p_x, *p_y0, *p_y1, *p_Wq, *p_Wp0, *p_Wp1, *p_Wp2, *p_Bp0, *p_Bp1, *p_vals;
    cudaGetSymbolAddress((void**)&p_x, d_x);
    cudaGetSymbolAddress((void**)&p_y0, d_y0);
    cudaGetSymbolAddress((void**)&p_y1, d_y1);
    cudaGetSymbolAddress((void**)&p_Wq, d_Wq);
    cudaGetSymbolAddress((void**)&p_Wp0, d_Wp0);
    cudaGetSymbolAddress((void**)&p_Wp1, d_Wp1);
    cudaGetSymbolAddress((void**)&p_Wp2, d_Wp2);
    cudaGetSymbolAddress((void**)&p_Bp0, d_Bp0);
    cudaGetSymbolAddress((void**)&p_Bp1, d_Bp1);
    cudaGetSymbolAddress((void**)&p_vals, d_vals);

    cudaFuncSetAttribute(k_attn, cudaFuncAttributeMaxDynamicSharedMemorySize, 48 * 1024);

    // dyn smem bytes
    const int smem16   = (16 * 8 * 72 + 2112) * 4;   // 45312 (qkv)
    const int smem11   = (11 * 8 * 72 + 2112) * 4;   // 33792 (mlp2)
    const int smem32_16 = (16 * 8 * 40 + 2112) * 4;  // 28928 (mlp0)
    const int smem32_14 = (14 * 8 * 40 + 2112) * 4;  // 26368 (mlp1)

    k_setup<<<NG + 354, 256>>>(h, nt, W_emb, batch, W_qkv, W_d0, b_d0, W_d1, b_d1, W_d2);
    k_gmma<16, 384, 0, 2><<<dim3(6, 128), 128, smem16>>>(p_x, p_Wq, b_qkv, nullptr);
    k_attn<<<NG * 4, 256, 9864 * 4>>>(pos, W_t, b_t, W_g, b_g);
    k_gmma32<16, 128, 128><<<dim3(4, 128), 64, smem32_16>>>(p_vals, p_Wp0, p_Bp0, p_y0);
    k_gmma32<14, 128, 128><<<dim3(4, 128), 64, smem32_14>>>(p_y0, p_Wp1, p_Bp1, p_y1);
    k_gmma<11, 64, 64, 1><<<dim3(1, 128), 128, smem11>>>(p_y1, p_Wp2, b_d2, out);
}